// round 7
// baseline (speedup 1.0000x reference)
#include <cuda_runtime.h>
#include <cuda_bf16.h>
#include <cstdint>

#define Tn   4096
#define INn  32
#define Hn   512
#define OUTn 32

#define TPB  512
#define L1C  26          // CTAs for layer 1 (NU=20 units each)
#define L23C 52          // CTAs for layers 2 and 3 (NU=10 units each)
#define NCTA (L1C + 2*L23C)   // 130

// -------- persistent device scratch --------
__device__ float g_X1[(size_t)Tn * 4 * Hn];
__device__ float g_h[3][(size_t)Tn * Hn];

// per-CTA progress flags, one 128B line each (monotonic across replays)
__device__ __align__(128) unsigned g_flag[3][64][32];
// one-time global barrier (X1 phase)
__device__ __align__(128) unsigned long long g_cnt[16];
__device__ __align__(128) unsigned long long g_gen[16];

__device__ __forceinline__ unsigned ld_acq(const unsigned* p) {
    unsigned v;
    asm volatile("ld.global.acquire.gpu.u32 %0, [%1];" : "=r"(v) : "l"(p) : "memory");
    return v;
}
__device__ __forceinline__ void st_rel(unsigned* p, unsigned v) {
    asm volatile("st.global.release.gpu.u32 [%0], %1;" :: "l"(p), "r"(v) : "memory");
}
__device__ __forceinline__ void ffma2(unsigned long long& d, unsigned long long a, unsigned long long b) {
    asm("fma.rn.f32x2 %0, %1, %2, %0;" : "+l"(d) : "l"(a), "l"(b));
}
__device__ __forceinline__ float f2lo(unsigned long long v) { return __uint_as_float((unsigned)v); }
__device__ __forceinline__ float f2hi(unsigned long long v) { return __uint_as_float((unsigned)(v >> 32)); }

__device__ __forceinline__ float fast_sig(float x) {
    x = fmaxf(x, -80.0f);
    return __fdividef(1.0f, 1.0f + __expf(-x));
}
__device__ __forceinline__ float fast_tanh(float x) {
    x = fminf(15.0f, fmaxf(-15.0f, x));
    float e = __expf(2.0f * x);
    return __fdividef(e - 1.0f, e + 1.0f);
}

#define RED(v) { v+=__shfl_xor_sync(0xffffffffu,v,16); v+=__shfl_xor_sync(0xffffffffu,v,8); \
                 v+=__shfl_xor_sync(0xffffffffu,v,4);  v+=__shfl_xor_sync(0xffffffffu,v,2); \
                 v+=__shfl_xor_sync(0xffffffffu,v,1); }

__global__ void __launch_bounds__(TPB, 1) lstm_flag_kernel(
    const float* __restrict__ seq,
    const float* __restrict__ Wih1, const float* __restrict__ Whh1,
    const float* __restrict__ bih1, const float* __restrict__ bhh1,
    const float* __restrict__ Wih2, const float* __restrict__ Whh2,
    const float* __restrict__ bih2, const float* __restrict__ bhh2,
    const float* __restrict__ Wih3, const float* __restrict__ Whh3,
    const float* __restrict__ bih3, const float* __restrict__ bhh3,
    const float* __restrict__ Wout, const float* __restrict__ bout,
    float* __restrict__ out)
{
    __shared__ float sh[Hn];            // own-layer h(t-1)
    __shared__ float sx[Hn];            // prev-layer h(t)
    __shared__ float spA[80];
    __shared__ float spB[40];
    __shared__ float sact[80];
    __shared__ float sc[20];
    __shared__ float sbias[40];
    __shared__ float sseq[32 * 33];
    __shared__ unsigned sbase[3];
    __shared__ unsigned long long sg3;

    const int tid = threadIdx.x;
    const int w = tid >> 5;
    const int lane = tid & 31;
    const int cta = blockIdx.x;

    // ---- capture flag bases (all layers) BEFORE the global barrier ----
    if (tid < 3) sbase[tid] = *(volatile unsigned*)&g_flag[tid][0][0];
    if (tid == 3) sg3 = *(volatile unsigned long long*)&g_gen[0];
    __syncthreads();

    // ================= Phase 0: X1 precompute =================
    {
        int row = cta * 16 + w;
        bool rv = row < 4 * Hn;
        float wx = rv ? Wih1[row * INn + lane] : 0.0f;
        float b1 = rv ? (bih1[row] + bhh1[row]) : 0.0f;
        for (int t0 = 0; t0 < Tn; t0 += 32) {
            __syncthreads();
            if (tid < 256) {
                const float4 v = *(const float4*)(seq + (size_t)t0 * INn + tid * 4);
                int tl = (tid * 4) >> 5, k = (tid * 4) & 31;
                float* p = &sseq[tl * 33 + k];
                p[0] = v.x; p[1] = v.y; p[2] = v.z; p[3] = v.w;
            }
            __syncthreads();
            float acc = 0.0f;
            #pragma unroll
            for (int k = 0; k < INn; k++)
                acc = fmaf(__shfl_sync(0xffffffffu, wx, k), sseq[lane * 33 + k], acc);
            if (rv) g_X1[(size_t)(t0 + lane) * (4 * Hn) + row] = acc + b1;
        }
    }
    // one-time global barrier
    if (tid == 0) {
        __threadfence();
        unsigned long long old = atomicAdd(&g_cnt[0], 1ULL);
        if (old == (unsigned long long)(NCTA - 1)) {
            g_cnt[0] = 0ULL;
            __threadfence();
            atomicAdd(&g_gen[0], 1ULL);
        }
        volatile unsigned long long* p = &g_gen[0];
        while (*p < sg3 + 1) { }
        __threadfence();
    }
    __syncthreads();

    // ================= group / layer assignment =================
    int layer, cg, gsz, NU, psz, NUp;
    if (cta < L1C)              { layer = 0; cg = cta;               gsz = L1C;  NU = 20; psz = 0;    NUp = 0; }
    else if (cta < L1C + L23C)  { layer = 1; cg = cta - L1C;         gsz = L23C; NU = 10; psz = L1C;  NUp = 20; }
    else                        { layer = 2; cg = cta - L1C - L23C;  gsz = L23C; NU = 10; psz = L23C; NUp = 10; }

    const float* Whh = (layer == 0) ? Whh1 : (layer == 1) ? Whh2 : Whh3;
    const float* Wih = (layer == 1) ? Wih2 : Wih3;
    const float* bih = (layer == 1) ? bih2 : bih3;
    const float* bhh = (layer == 1) ? bhh2 : bhh3;

    // ---- load 5 full 512-long weight rows per warp as f32x2 pairs ----
    unsigned long long wr2[40];
    #pragma unroll
    for (int u = 0; u < 5; u++) {
        int R; bool v;
        if (layer == 0) {
            int r = w * 5 + u;                 // 0..79
            int gate = r / 20, j = r % 20;
            int un = cg * 20 + j;
            v = un < Hn;
            R = gate * Hn + (v ? un : 0);
        } else {
            int rr = (w & 7) * 5 + u;          // 0..39
            int gate = rr / 10, j = rr % 10;
            int un = cg * 10 + j;
            v = un < Hn;
            R = gate * Hn + (v ? un : 0);
        }
        const float* W = (layer == 0) ? Whh : ((w < 8) ? Whh : Wih);
        #pragma unroll
        for (int p = 0; p < 8; p++)
            wr2[u * 8 + p] = v ? *(const unsigned long long*)(W + (size_t)R * Hn + p * 64 + 2 * lane) : 0ULL;
    }
    if (layer > 0 && tid < 40) {
        int gate = tid / 10, j = tid % 10;
        int un = cg * 10 + j;
        bool v = un < Hn;
        int R = gate * Hn + (v ? un : 0);
        sbias[tid] = v ? (bih[R] + bhh[R]) : 0.0f;
    }

    for (int i = tid; i < Hn; i += TPB) { sh[i] = 0.0f; sx[i] = 0.0f; }
    if (tid < 20) sc[tid] = 0.0f;
    __syncthreads();

    const unsigned baseO = sbase[layer];
    const unsigned baseP = (layer > 0) ? sbase[layer - 1] : 0u;
    float* hcur = g_h[layer];
    const float* hprev = (layer > 0) ? g_h[layer - 1] : nullptr;

    // ================= recurrence (pipelined across layer groups) =================
    for (int t = 0; t < Tn; t++) {
        // layer-0 x-part prefetch (in flight during the wait)
        float xv = 0.0f;
        if (layer == 0 && tid < 80) {
            int gate = tid / 20, j = tid % 20;
            int un = cg * 20 + j;
            if (un < Hn) xv = g_X1[(size_t)t * (4 * Hn) + gate * Hn + un];
        }

        // ---- fused wait + chunk load: each poller owns one producer CTA ----
        if (tid < gsz) {
            unsigned tgt = baseO + (unsigned)t;
            const unsigned* fp = &g_flag[layer][tid][0];
            while ((int)(ld_acq(fp) - tgt) < 0) { }
            if (t > 0) {
                const float* src = hcur + (size_t)(t - 1) * Hn + tid * NU;
                int base = tid * NU;
                #pragma unroll 10
                for (int k = 0; k < NU; k += 2) {
                    if (base + k < Hn)
                        *(unsigned long long*)&sh[base + k] = *(const unsigned long long*)(src + k);
                }
            }
        }
        if (layer > 0 && tid >= 64 && tid < 64 + psz) {
            int i = tid - 64;
            unsigned tgt = baseP + (unsigned)(t + 1);
            const unsigned* fp = &g_flag[layer - 1][i][0];
            while ((int)(ld_acq(fp) - tgt) < 0) { }
            const float* src = hprev + (size_t)t * Hn + i * NUp;
            int base = i * NUp;
            #pragma unroll 10
            for (int k = 0; k < NUp; k += 2) {
                if (base + k < Hn)
                    *(unsigned long long*)&sx[base + k] = *(const unsigned long long*)(src + k);
            }
        }
        __syncthreads();

        // ---- 5 x 512 dot products per warp (f32x2 packed FMA) ----
        const float* src = (layer > 0 && w >= 8) ? sx : sh;
        unsigned long long a0 = 0, a1 = 0, a2 = 0, a3 = 0, a4 = 0;
        #pragma unroll
        for (int p = 0; p < 8; p++) {
            unsigned long long hv = *(const unsigned long long*)&src[p * 64 + 2 * lane];
            ffma2(a0, wr2[p],      hv);
            ffma2(a1, wr2[8 + p],  hv);
            ffma2(a2, wr2[16 + p], hv);
            ffma2(a3, wr2[24 + p], hv);
            ffma2(a4, wr2[32 + p], hv);
        }
        float r0 = f2lo(a0) + f2hi(a0);
        float r1 = f2lo(a1) + f2hi(a1);
        float r2 = f2lo(a2) + f2hi(a2);
        float r3 = f2lo(a3) + f2hi(a3);
        float r4 = f2lo(a4) + f2hi(a4);
        RED(r0) RED(r1) RED(r2) RED(r3) RED(r4)
        if (lane < 5) {
            float v = (lane == 0) ? r0 : (lane == 1) ? r1 : (lane == 2) ? r2 : (lane == 3) ? r3 : r4;
            if (layer == 0) spA[w * 5 + lane] = v;
            else            ((w < 8) ? spA : spB)[(w & 7) * 5 + lane] = v;
        }
        __syncthreads();

        // ---- activations ----
        if (layer == 0) {
            if (tid < 80) {
                float gv = spA[tid] + xv;
                int gate = tid / 20;
                sact[tid] = (gate == 2) ? fast_tanh(gv) : fast_sig(gv);
            }
        } else {
            if (tid < 40) {
                float gv = spA[tid] + spB[tid] + sbias[tid];
                int gate = tid / 10;
                sact[tid] = (gate == 2) ? fast_tanh(gv) : fast_sig(gv);
            }
        }
        __syncthreads();

        // ---- c/h update + store ----
        if (tid < NU) {
            int un = cg * NU + tid;
            float iv = sact[tid], fv = sact[NU + tid], gg = sact[2 * NU + tid], ov = sact[3 * NU + tid];
            float c = fmaf(fv, sc[tid], iv * gg);
            sc[tid] = c;
            if (un < Hn) hcur[(size_t)t * Hn + un] = ov * fast_tanh(c);
        }
        __syncthreads();                       // h stores happen-before the release below
        if (tid == 0) st_rel(&g_flag[layer][cg][0], baseO + (unsigned)(t + 1));
    }

    // ================= final projection =================
    if (tid < L23C) {
        unsigned tgt = sbase[2] + (unsigned)Tn;
        const unsigned* fp = &g_flag[2][tid][0];
        while ((int)(ld_acq(fp) - tgt) < 0) { }
    }
    __syncthreads();

    float wo[32];
    const int o0 = w * 2;
    #pragma unroll
    for (int i = 0; i < 16; i++) {
        wo[i]      = Wout[(size_t)o0 * Hn + i * 32 + lane];
        wo[16 + i] = Wout[(size_t)(o0 + 1) * Hn + i * 32 + lane];
    }
    const float b0 = bout[o0], b1o = bout[o0 + 1];
    const float* h3 = g_h[2];
    for (int t = cta; t < Tn; t += NCTA) {
        __syncthreads();
        if (tid < 128)
            *(float4*)&sh[tid * 4] = *(const float4*)(h3 + (size_t)t * Hn + tid * 4);
        __syncthreads();
        float a0 = 0, a1 = 0;
        #pragma unroll
        for (int i = 0; i < 16; i++) {
            float hv = sh[i * 32 + lane];
            a0 = fmaf(wo[i],      hv, a0);
            a1 = fmaf(wo[16 + i], hv, a1);
        }
        RED(a0) RED(a1)
        if (lane == 0) out[(size_t)t * OUTn + o0]     = a0 + b0;
        if (lane == 1) out[(size_t)t * OUTn + o0 + 1] = a1 + b1o;
    }
}

extern "C" void kernel_launch(void* const* d_in, const int* in_sizes, int n_in,
                              void* d_out, int out_size) {
    const float* seq  = (const float*)d_in[0];
    const float* Wih1 = (const float*)d_in[1];
    const float* Whh1 = (const float*)d_in[2];
    const float* bih1 = (const float*)d_in[3];
    const float* bhh1 = (const float*)d_in[4];
    const float* Wih2 = (const float*)d_in[5];
    const float* Whh2 = (const float*)d_in[6];
    const float* bih2 = (const float*)d_in[7];
    const float* bhh2 = (const float*)d_in[8];
    const float* Wih3 = (const float*)d_in[9];
    const float* Whh3 = (const float*)d_in[10];
    const float* bih3 = (const float*)d_in[11];
    const float* bhh3 = (const float*)d_in[12];
    const float* Wout = (const float*)d_in[13];
    const float* bout = (const float*)d_in[14];
    float* out = (float*)d_out;

    lstm_flag_kernel<<<NCTA, TPB>>>(seq,
        Wih1, Whh1, bih1, bhh1,
        Wih2, Whh2, bih2, bhh2,
        Wih3, Whh3, bih3, bhh3,
        Wout, bout, out);
}

// round 8
// speedup vs baseline: 1.0447x; 1.0447x over previous
#include <cuda_runtime.h>
#include <cstdint>
typedef unsigned long long ULL;

#define Tn   4096
#define INn  32
#define Hn   512
#define OUTn 32
#define TPB  256
#define CLC  16
#define NCTA 112
#define SMEM_SZ (104*1024)

// dynamic smem layout (bytes)
#define OFF_HBUF 98304
#define OFF_XBUF 102400
#define OFF_SP   102912
#define OFF_HSTG 103424

__device__ float g_X[3][(size_t)Tn * 2048];     // gate-major x-parts (incl. bias)
__device__ float g_h[3][(size_t)Tn * Hn];
__device__ __align__(128) unsigned g_hflag[3][16][32];
__device__ __align__(128) unsigned g_xflag[2][2][16][32];   // [which X][parity][crank]
__device__ __align__(128) ULL g_cnt[16];
__device__ __align__(128) ULL g_gen[16];

__device__ __forceinline__ unsigned ld_acq(const unsigned* p) {
    unsigned v; asm volatile("ld.global.acquire.gpu.u32 %0, [%1];" : "=r"(v) : "l"(p) : "memory"); return v;
}
__device__ __forceinline__ void st_rel(unsigned* p, unsigned v) {
    asm volatile("st.global.release.gpu.u32 [%0], %1;" :: "l"(p), "r"(v) : "memory");
}
__device__ __forceinline__ void ffma2(ULL& d, ULL a, ULL b) {
    asm("fma.rn.f32x2 %0, %1, %2, %0;" : "+l"(d) : "l"(a), "l"(b));
}
__device__ __forceinline__ float f2lo(ULL v) { return __uint_as_float((unsigned)v); }
__device__ __forceinline__ float f2hi(ULL v) { return __uint_as_float((unsigned)(v >> 32)); }
__device__ __forceinline__ uint32_t smem_u32(const void* p) {
    uint32_t a; asm("{ .reg .u64 t; cvta.to.shared.u64 t, %1; cvt.u32.u64 %0, t; }" : "=r"(a) : "l"(p)); return a;
}
__device__ __forceinline__ uint32_t mapa_rank(uint32_t la, uint32_t r) {
    uint32_t o; asm("mapa.shared::cluster.u32 %0, %1, %2;" : "=r"(o) : "r"(la), "r"(r)); return o;
}
__device__ __forceinline__ void st_cluster_f32(uint32_t a, float v) {
    asm volatile("st.shared::cluster.f32 [%0], %1;" :: "r"(a), "f"(v) : "memory");
}
__device__ __forceinline__ void mbar_init(uint32_t a, unsigned c) {
    asm volatile("mbarrier.init.shared.b64 [%0], %1;" :: "r"(a), "r"(c) : "memory");
}
__device__ __forceinline__ void mbar_arrive_cl(uint32_t a) {
    asm volatile("mbarrier.arrive.release.cluster.shared::cluster.b64 _, [%0];" :: "r"(a) : "memory");
}
__device__ __forceinline__ void mbar_wait(uint32_t a, unsigned par) {
    unsigned done;
    do {
        asm volatile("{\n\t.reg .pred p;\n\t"
            "mbarrier.try_wait.parity.acquire.cluster.shared::cta.b64 p, [%1], %2, 0x989680;\n\t"
            "selp.b32 %0, 1, 0, p;\n\t}"
            : "=r"(done) : "r"(a), "r"(par) : "memory");
    } while (!done);
}
__device__ __forceinline__ float fast_sig(float x) {
    x = fmaxf(x, -80.0f); return __fdividef(1.0f, 1.0f + __expf(-x));
}
__device__ __forceinline__ float fast_tanh(float x) {
    x = fminf(15.0f, fmaxf(-15.0f, x));
    float e = __expf(2.0f * x); return __fdividef(e - 1.0f, e + 1.0f);
}
#define RED16(v) { v+=__shfl_xor_sync(0xffffffffu,v,1); v+=__shfl_xor_sync(0xffffffffu,v,2); \
                   v+=__shfl_xor_sync(0xffffffffu,v,4); v+=__shfl_xor_sync(0xffffffffu,v,8); }
#define RED32(v) { v+=__shfl_xor_sync(0xffffffffu,v,16); RED16(v) }

__global__ void __launch_bounds__(TPB, 1) lstm_cluster_kernel(
    const float* __restrict__ seq,
    const float* __restrict__ Wih1, const float* __restrict__ Whh1,
    const float* __restrict__ bih1, const float* __restrict__ bhh1,
    const float* __restrict__ Wih2, const float* __restrict__ Whh2,
    const float* __restrict__ bih2, const float* __restrict__ bhh2,
    const float* __restrict__ Wih3, const float* __restrict__ Whh3,
    const float* __restrict__ bih3, const float* __restrict__ bhh3,
    const float* __restrict__ Wout, const float* __restrict__ bout,
    float* __restrict__ out)
{
    extern __shared__ char dsm[];
    ULL*   wsm    = (ULL*)dsm;
    float* hbuf   = (float*)(dsm + OFF_HBUF);   // 2 x 512
    float* xbuf   = (float*)(dsm + OFF_XBUF);   // 128
    float* sp     = (float*)(dsm + OFF_SP);     // 128
    float* hstage = (float*)(dsm + OFF_HSTG);   // 32
    float* sseq   = (float*)dsm;                // phase-0 alias

    __shared__ ULL mbar[2];
    __shared__ unsigned sbh[3], sbx[4];
    __shared__ ULL sg;

    const int tid = threadIdx.x, w = tid >> 5, lane = tid & 31;
    const int hf = lane >> 4, l16 = lane & 15;
    const int cta = blockIdx.x, clu = cta >> 4, crank = cta & 15;

    if (tid < 3) sbh[tid] = *(volatile unsigned*)&g_hflag[tid][0][0];
    if (tid >= 3 && tid < 7) sbx[tid-3] = *(volatile unsigned*)&g_xflag[(tid-3)>>1][(tid-3)&1][0][0];
    if (tid == 7) sg = *(volatile ULL*)&g_gen[0];
    __syncthreads();

    // ================= Phase 0: X1 = seq @ Wih1^T + b =================
    {
        float wx[3], bb[3];
        #pragma unroll
        for (int p = 0; p < 3; p++) {
            int row = cta * 8 + w + p * 896;
            bool v = row < 2048; int R = v ? row : 0;
            wx[p] = v ? Wih1[R * INn + lane] : 0.0f;
            bb[p] = v ? (bih1[R] + bhh1[R]) : 0.0f;
        }
        for (int t0 = 0; t0 < Tn; t0 += 32) {
            __syncthreads();
            {
                const float4 v = *(const float4*)(seq + (size_t)t0 * INn + tid * 4);
                int tl = (tid * 4) >> 5, k = (tid * 4) & 31;
                float* pp = &sseq[tl * 33 + k];
                pp[0] = v.x; pp[1] = v.y; pp[2] = v.z; pp[3] = v.w;
            }
            __syncthreads();
            #pragma unroll
            for (int p = 0; p < 3; p++) {
                int row = cta * 8 + w + p * 896;
                if (row < 2048) {
                    float acc = 0.0f;
                    #pragma unroll
                    for (int k = 0; k < INn; k++)
                        acc = fmaf(__shfl_sync(0xffffffffu, wx[p], k), sseq[lane * 33 + k], acc);
                    g_X[0][(size_t)(t0 + lane) * 2048 + row] = acc + bb[p];
                }
            }
        }
    }
    __syncthreads();

    // ================= role assignment + weight fill =================
    const bool rec = (clu < 3);
    int xi = 0, par = 0, up = 0;
    const float* W; const float* fbi = bih2; const float* fbh = bhh2;
    if (rec) {
        W = (clu == 0) ? Whh1 : (clu == 1) ? Whh2 : Whh3;
    } else {
        int f = clu - 3; xi = f >> 1; par = f & 1; up = xi;
        W = (xi == 0) ? Wih2 : Wih3;
        fbi = (xi == 0) ? bih2 : bih3; fbh = (xi == 0) ? bhh2 : bhh3;
    }

    ULL wreg[80];
    float fb[8];
    #pragma unroll
    for (int i = 0; i < 5; i++) {
        int rl = w * 16 + hf * 8 + i;
        size_t R = (size_t)((rl >> 5) * Hn + crank * 32 + (rl & 31));
        #pragma unroll
        for (int j = 0; j < 16; j++)
            wreg[i * 16 + j] = *(const ULL*)(W + R * Hn + l16 * 32 + j * 2);
    }
    #pragma unroll
    for (int s = 0; s < 3; s++) {
        int rl = w * 16 + hf * 8 + 5 + s;
        size_t R = (size_t)((rl >> 5) * Hn + crank * 32 + (rl & 31));
        #pragma unroll
        for (int j = 0; j < 16; j++)
            wsm[(((w * 3 + s) * 16 + j) << 5) + lane] = *(const ULL*)(W + R * Hn + l16 * 32 + j * 2);
    }
    #pragma unroll
    for (int i = 0; i < 8; i++) {
        int rl = w * 16 + hf * 8 + i;
        int R = (rl >> 5) * Hn + crank * 32 + (rl & 31);
        fb[i] = rec ? 0.0f : (fbi[R] + fbh[R]);
    }

    *(float4*)&hbuf[tid * 4] = make_float4(0.f, 0.f, 0.f, 0.f);
    if (rec && tid == 0) { mbar_init(smem_u32(&mbar[0]), 16); mbar_init(smem_u32(&mbar[1]), 16); }
    __syncthreads();
    if (rec) {
        asm volatile("barrier.cluster.arrive.aligned;" ::: "memory");
        asm volatile("barrier.cluster.wait.aligned;" ::: "memory");
    }

    // one-time global barrier
    if (tid == 0) {
        __threadfence();
        ULL old = atomicAdd(&g_cnt[0], 1ULL);
        if (old == (ULL)(NCTA - 1)) {
            g_cnt[0] = 0ULL; __threadfence(); atomicAdd(&g_gen[0], 1ULL);
        }
        volatile ULL* p = &g_gen[0];
        while (*p < sg + 1) { }
        __threadfence();
    }
    __syncthreads();

    if (rec) {
        // ================= recurrent cluster, layer = clu =================
        const unsigned hb = sbh[clu];
        unsigned* myf = &g_hflag[clu][crank][0];
        float* hout = g_h[clu];
        const float* Xs = g_X[clu];
        const unsigned* xf0 = (clu > 0) ? &g_xflag[clu-1][0][crank][0] : (const unsigned*)0;
        const unsigned* xf1 = (clu > 0) ? &g_xflag[clu-1][1][crank][0] : (const unsigned*)0;
        const unsigned xb0 = (clu > 0) ? sbx[(clu-1)*2+0] : 0u;
        const unsigned xb1 = (clu > 0) ? sbx[(clu-1)*2+1] : 0u;

        const uint32_t mb0 = smem_u32(&mbar[0]);
        const uint32_t hsl = smem_u32(&hbuf[crank * 32 + lane]);
        const uint32_t rdA = mapa_rank(hsl, (uint32_t)w);
        const uint32_t rdB = mapa_rank(hsl, (uint32_t)(w + 8));
        const uint32_t baA = mapa_rank(mb0, (uint32_t)w);
        const uint32_t baB = mapa_rank(mb0, (uint32_t)(w + 8));
        float creg = 0.0f;

        for (int t = 0; t < Tn; t++) {
            if (tid >= 224) {      // warp 7: X loaders (poll feeder flag for layers 1/2)
                int idx = tid - 224, gate = idx >> 3, ch = idx & 7;
                if (clu > 0) {
                    const unsigned* fp = (t & 1) ? xf1 : xf0;
                    unsigned tgt = ((t & 1) ? xb1 : xb0) + (unsigned)((t >> 1) + 1);
                    while ((int)(ld_acq(fp) - tgt) < 0) { }
                }
                *(float4*)&xbuf[gate * 32 + ch * 4] =
                    *(const float4*)(Xs + (size_t)t * 2048 + gate * 512 + crank * 32 + ch * 4);
            }
            if (t > 0 && tid == 0)
                mbar_wait(mb0 + ((t - 1) & 1) * 8, (unsigned)(((t - 1) >> 1) & 1));
            __syncthreads();

            const ULL* hsrc = (const ULL*)(hbuf + ((t + 1) & 1) * 512);
            ULL a0=0,a1=0,a2=0,a3=0,a4=0,a5=0,a6=0,a7=0;
            #pragma unroll
            for (int j = 0; j < 16; j++) {
                ULL hv = hsrc[l16 * 16 + j];
                ffma2(a0, wreg[j], hv);       ffma2(a1, wreg[16+j], hv);
                ffma2(a2, wreg[32+j], hv);    ffma2(a3, wreg[48+j], hv);
                ffma2(a4, wreg[64+j], hv);
                ffma2(a5, wsm[(((w*3+0)*16+j)<<5)+lane], hv);
                ffma2(a6, wsm[(((w*3+1)*16+j)<<5)+lane], hv);
                ffma2(a7, wsm[(((w*3+2)*16+j)<<5)+lane], hv);
            }
            float r0=f2lo(a0)+f2hi(a0), r1=f2lo(a1)+f2hi(a1), r2=f2lo(a2)+f2hi(a2), r3=f2lo(a3)+f2hi(a3);
            float r4=f2lo(a4)+f2hi(a4), r5=f2lo(a5)+f2hi(a5), r6=f2lo(a6)+f2hi(a6), r7=f2lo(a7)+f2hi(a7);
            RED16(r0) RED16(r1) RED16(r2) RED16(r3) RED16(r4) RED16(r5) RED16(r6) RED16(r7)
            if (l16 == 0) {
                int rb = w * 16 + hf * 8;
                sp[rb]=r0; sp[rb+1]=r1; sp[rb+2]=r2; sp[rb+3]=r3;
                sp[rb+4]=r4; sp[rb+5]=r5; sp[rb+6]=r6; sp[rb+7]=r7;
            }
            __syncthreads();

            if (tid < 32) {
                float pi = sp[tid] + xbuf[tid];
                float pf = sp[32+tid] + xbuf[32+tid];
                float pg = sp[64+tid] + xbuf[64+tid];
                float po = sp[96+tid] + xbuf[96+tid];
                float iv = fast_sig(pi), fv = fast_sig(pf);
                float gg = fast_tanh(pg), ov = fast_sig(po);
                creg = fmaf(fv, creg, iv * gg);
                float h = ov * fast_tanh(creg);
                hstage[tid] = h;
                hout[(size_t)t * Hn + crank * 32 + tid] = h;
            }
            __syncthreads();

            {   // distribute h chunk: warp w -> ranks w and w+8, buffer t&1
                float hv = hstage[lane];
                unsigned off = (unsigned)(t & 1) * 2048u;
                st_cluster_f32(rdA + off, hv);
                st_cluster_f32(rdB + off, hv);
                __syncwarp();
                asm volatile("fence.acq_rel.cluster;" ::: "memory");
                if (lane == 0) {
                    unsigned bo = (unsigned)(t & 1) * 8u;
                    mbar_arrive_cl(baA + bo);
                    mbar_arrive_cl(baB + bo);
                }
            }
            if (tid == 0) st_rel(myf, hb + (unsigned)(t + 1));
        }
        asm volatile("barrier.cluster.arrive.aligned;" ::: "memory");
        asm volatile("barrier.cluster.wait.aligned;" ::: "memory");
    } else {
        // ================= feeder: X[xi+1][t] = W . g_h[up][t] + b, t parity = par =================
        const unsigned ub = sbh[up];
        const unsigned xb = sbx[xi * 2 + par];
        unsigned* myf = &g_xflag[xi][par][crank][0];
        float* Xd = g_X[xi + 1];
        const float* hg = g_h[up];

        for (int t = par; t < Tn; t += 2) {
            if (tid < 16) {
                unsigned tgt = ub + (unsigned)(t + 1);
                const unsigned* fp = &g_hflag[up][tid][0];
                while ((int)(ld_acq(fp) - tgt) < 0) { }
                const float4* s4 = (const float4*)(hg + (size_t)t * Hn + tid * 32);
                float4* d4 = (float4*)(hbuf + tid * 32);
                #pragma unroll
                for (int q = 0; q < 8; q++) d4[q] = s4[q];
            }
            __syncthreads();

            const ULL* hsrc = (const ULL*)hbuf;
            ULL a0=0,a1=0,a2=0,a3=0,a4=0,a5=0,a6=0,a7=0;
            #pragma unroll
            for (int j = 0; j < 16; j++) {
                ULL hv = hsrc[l16 * 16 + j];
                ffma2(a0, wreg[j], hv);       ffma2(a1, wreg[16+j], hv);
                ffma2(a2, wreg[32+j], hv);    ffma2(a3, wreg[48+j], hv);
                ffma2(a4, wreg[64+j], hv);
                ffma2(a5, wsm[(((w*3+0)*16+j)<<5)+lane], hv);
                ffma2(a6, wsm[(((w*3+1)*16+j)<<5)+lane], hv);
                ffma2(a7, wsm[(((w*3+2)*16+j)<<5)+lane], hv);
            }
            float rr[8];
            rr[0]=f2lo(a0)+f2hi(a0); rr[1]=f2lo(a1)+f2hi(a1); rr[2]=f2lo(a2)+f2hi(a2); rr[3]=f2lo(a3)+f2hi(a3);
            rr[4]=f2lo(a4)+f2hi(a4); rr[5]=f2lo(a5)+f2hi(a5); rr[6]=f2lo(a6)+f2hi(a6); rr[7]=f2lo(a7)+f2hi(a7);
            #pragma unroll
            for (int i = 0; i < 8; i++) { RED16(rr[i]) }
            if (l16 == 0) {
                int rb = w * 16 + hf * 8;
                #pragma unroll
                for (int i = 0; i < 8; i++) {
                    int rl = rb + i;
                    Xd[(size_t)t * 2048 + (rl >> 5) * 512 + crank * 32 + (rl & 31)] = rr[i] + fb[i];
                }
            }
            __syncthreads();
            if (tid == 0) st_rel(myf, xb + (unsigned)((t >> 1) + 1));
        }
    }

    // ================= final projection (all CTAs) =================
    if (tid < 16) {
        unsigned tgt = sbh[2] + (unsigned)Tn;
        const unsigned* fp = &g_hflag[2][tid][0];
        while ((int)(ld_acq(fp) - tgt) < 0) { }
    }
    __syncthreads();

    ULL wo[32];
    float bo4[4];
    #pragma unroll
    for (int oi = 0; oi < 4; oi++) {
        int o = w * 4 + oi;
        #pragma unroll
        for (int j = 0; j < 8; j++)
            wo[oi * 8 + j] = *(const ULL*)(Wout + (size_t)o * Hn + j * 64 + lane * 2);
        bo4[oi] = bout[o];
    }
    const float* h3 = g_h[2];
    for (int t = cta; t < Tn; t += NCTA) {
        __syncthreads();
        if (tid < 128)
            *(float4*)&hbuf[tid * 4] = *(const float4*)(h3 + (size_t)t * Hn + tid * 4);
        __syncthreads();
        const ULL* hh = (const ULL*)hbuf;
        #pragma unroll
        for (int oi = 0; oi < 4; oi++) {
            ULL acc = 0;
            #pragma unroll
            for (int j = 0; j < 8; j++) ffma2(acc, wo[oi * 8 + j], hh[j * 32 + lane]);
            float r = f2lo(acc) + f2hi(acc);
            RED32(r)
            if (lane == 0) out[(size_t)t * OUTn + w * 4 + oi] = r + bo4[oi];
        }
    }
}

extern "C" void kernel_launch(void* const* d_in, const int* in_sizes, int n_in,
                              void* d_out, int out_size) {
    const float* seq  = (const float*)d_in[0];
    const float* Wih1 = (const float*)d_in[1];
    const float* Whh1 = (const float*)d_in[2];
    const float* bih1 = (const float*)d_in[3];
    const float* bhh1 = (const float*)d_in[4];
    const float* Wih2 = (const float*)d_in[5];
    const float* Whh2 = (const float*)d_in[6];
    const float* bih2 = (const float*)d_in[7];
    const float* bhh2 = (const float*)d_in[8];
    const float* Wih3 = (const float*)d_in[9];
    const float* Whh3 = (const float*)d_in[10];
    const float* bih3 = (const float*)d_in[11];
    const float* bhh3 = (const float*)d_in[12];
    const float* Wout = (const float*)d_in[13];
    const float* bout = (const float*)d_in[14];
    float* out = (float*)d_out;

    cudaFuncSetAttribute(lstm_cluster_kernel, cudaFuncAttributeMaxDynamicSharedMemorySize, SMEM_SZ);
    cudaFuncSetAttribute(lstm_cluster_kernel, cudaFuncAttributeNonPortableClusterSizeAllowed, 1);

    cudaLaunchConfig_t cfg = {};
    cfg.gridDim = {NCTA, 1, 1};
    cfg.blockDim = {TPB, 1, 1};
    cfg.dynamicSmemBytes = SMEM_SZ;
    cudaLaunchAttribute at[1];
    at[0].id = cudaLaunchAttributeClusterDimension;
    at[0].val.clusterDim = {CLC, 1, 1};
    cfg.attrs = at;
    cfg.numAttrs = 1;

    cudaLaunchKernelEx(&cfg, lstm_cluster_kernel, seq,
        Wih1, Whh1, bih1, bhh1,
        Wih2, Whh2, bih2, bhh2,
        Wih3, Whh3, bih3, bhh3,
        Wout, bout, out);
}

// round 10
// speedup vs baseline: 1.2596x; 1.2057x over previous
#include <cuda_runtime.h>
#include <cstdint>
typedef unsigned long long ULL;

#define Tn   4096
#define INn  32
#define Hn   512
#define OUTn 32
#define TPB  256
#define CLC  16
#define NCTA 112

// dynamic smem layout (bytes): weights 8 warps x 4 slots x 16 j x 32 lanes x 8B
#define OFF_HBUF 131072
#define OFF_XBUF 135168
#define OFF_SP   135680
#define OFF_HSTG 136192
#define SMEM_SZ  136448

__device__ float g_X[3][(size_t)Tn * 2048];     // gate-major x-parts (incl. bias)
__device__ float g_h[3][(size_t)Tn * Hn];
__device__ __align__(128) unsigned g_hflag[3][16][32];
__device__ __align__(128) unsigned g_xflag[2][2][16][32];   // [which X][parity][crank]
__device__ __align__(128) ULL g_cnt[16];
__device__ __align__(128) ULL g_gen[16];

__device__ __forceinline__ unsigned ld_acq(const unsigned* p) {
    unsigned v; asm volatile("ld.global.acquire.gpu.u32 %0, [%1];" : "=r"(v) : "l"(p) : "memory"); return v;
}
__device__ __forceinline__ void st_rel(unsigned* p, unsigned v) {
    asm volatile("st.global.release.gpu.u32 [%0], %1;" :: "l"(p), "r"(v) : "memory");
}
__device__ __forceinline__ void ffma2(ULL& d, ULL a, ULL b) {
    asm("fma.rn.f32x2 %0, %1, %2, %0;" : "+l"(d) : "l"(a), "l"(b));
}
__device__ __forceinline__ float f2lo(ULL v) { return __uint_as_float((unsigned)v); }
__device__ __forceinline__ float f2hi(ULL v) { return __uint_as_float((unsigned)(v >> 32)); }
__device__ __forceinline__ uint32_t smem_u32(const void* p) {
    uint32_t a; asm("{ .reg .u64 t; cvta.to.shared.u64 t, %1; cvt.u32.u64 %0, t; }" : "=r"(a) : "l"(p)); return a;
}
__device__ __forceinline__ uint32_t mapa_rank(uint32_t la, uint32_t r) {
    uint32_t o; asm("mapa.shared::cluster.u32 %0, %1, %2;" : "=r"(o) : "r"(la), "r"(r)); return o;
}
__device__ __forceinline__ void st_cluster_f32(uint32_t a, float v) {
    asm volatile("st.shared::cluster.f32 [%0], %1;" :: "r"(a), "f"(v) : "memory");
}
__device__ __forceinline__ void mbar_init(uint32_t a, unsigned c) {
    asm volatile("mbarrier.init.shared.b64 [%0], %1;" :: "r"(a), "r"(c) : "memory");
}
__device__ __forceinline__ void mbar_arrive_cl(uint32_t a) {
    asm volatile("mbarrier.arrive.release.cluster.shared::cluster.b64 _, [%0];" :: "r"(a) : "memory");
}
__device__ __forceinline__ void mbar_wait(uint32_t a, unsigned par) {
    unsigned done;
    do {
        asm volatile("{\n\t.reg .pred p;\n\t"
            "mbarrier.try_wait.parity.acquire.cluster.shared::cta.b64 p, [%1], %2, 0x989680;\n\t"
            "selp.b32 %0, 1, 0, p;\n\t}"
            : "=r"(done) : "r"(a), "r"(par) : "memory");
    } while (!done);
}
__device__ __forceinline__ float fast_sig(float x) {
    x = fmaxf(x, -80.0f); return __fdividef(1.0f, 1.0f + __expf(-x));
}
__device__ __forceinline__ float fast_tanh(float x) {
    x = fminf(15.0f, fmaxf(-15.0f, x));
    float e = __expf(2.0f * x); return __fdividef(e - 1.0f, e + 1.0f);
}
#define RED16(v) { v+=__shfl_xor_sync(0xffffffffu,v,1); v+=__shfl_xor_sync(0xffffffffu,v,2); \
                   v+=__shfl_xor_sync(0xffffffffu,v,4); v+=__shfl_xor_sync(0xffffffffu,v,8); }
#define RED32(v) { v+=__shfl_xor_sync(0xffffffffu,v,16); RED16(v) }

__global__ void __launch_bounds__(TPB, 1) lstm_cluster2_kernel(
    const float* __restrict__ seq,
    const float* __restrict__ Wih1, const float* __restrict__ Whh1,
    const float* __restrict__ bih1, const float* __restrict__ bhh1,
    const float* __restrict__ Wih2, const float* __restrict__ Whh2,
    const float* __restrict__ bih2, const float* __restrict__ bhh2,
    const float* __restrict__ Wih3, const float* __restrict__ Whh3,
    const float* __restrict__ bih3, const float* __restrict__ bhh3,
    const float* __restrict__ Wout, const float* __restrict__ bout,
    float* __restrict__ out)
{
    extern __shared__ char dsm[];
    ULL*   wsm    = (ULL*)dsm;                  // 128 KB weights (4 rows per half-warp)
    float* hbuf   = (float*)(dsm + OFF_HBUF);   // 2 x 512, SWIZZLED ULL layout
    float* xbuf   = (float*)(dsm + OFF_XBUF);   // 128
    float* sp     = (float*)(dsm + OFF_SP);     // 128
    float* hstage = (float*)(dsm + OFF_HSTG);   // 32 (linear)
    float* sseq   = (float*)dsm;                // phase-0 alias

    __shared__ ULL mbar[2];
    __shared__ unsigned sbh[3], sbx[4];
    __shared__ ULL sg;

    const int tid = threadIdx.x, w = tid >> 5, lane = tid & 31;
    const int hf = lane >> 4, l16 = lane & 15;
    const int cta = blockIdx.x, clu = cta >> 4, crank = cta & 15;

    if (tid < 3) sbh[tid] = *(volatile unsigned*)&g_hflag[tid][0][0];
    if (tid >= 3 && tid < 7) sbx[tid-3] = *(volatile unsigned*)&g_xflag[(tid-3)>>1][(tid-3)&1][0][0];
    if (tid == 7) sg = *(volatile ULL*)&g_gen[0];
    __syncthreads();

    // ================= Phase 0: X1 = seq @ Wih1^T + b =================
    {
        float wx[3], bb[3];
        #pragma unroll
        for (int p = 0; p < 3; p++) {
            int row = cta * 8 + w + p * 896;
            bool v = row < 2048; int R = v ? row : 0;
            wx[p] = v ? Wih1[R * INn + lane] : 0.0f;
            bb[p] = v ? (bih1[R] + bhh1[R]) : 0.0f;
        }
        for (int t0 = 0; t0 < Tn; t0 += 32) {
            __syncthreads();
            {
                const float4 v = *(const float4*)(seq + (size_t)t0 * INn + tid * 4);
                int tl = (tid * 4) >> 5, k = (tid * 4) & 31;
                float* pp = &sseq[tl * 33 + k];
                pp[0] = v.x; pp[1] = v.y; pp[2] = v.z; pp[3] = v.w;
            }
            __syncthreads();
            #pragma unroll
            for (int p = 0; p < 3; p++) {
                int row = cta * 8 + w + p * 896;
                if (row < 2048) {
                    float acc = 0.0f;
                    #pragma unroll
                    for (int k = 0; k < INn; k++)
                        acc = fmaf(__shfl_sync(0xffffffffu, wx[p], k), sseq[lane * 33 + k], acc);
                    g_X[0][(size_t)(t0 + lane) * 2048 + row] = acc + bb[p];
                }
            }
        }
    }
    __syncthreads();

    // ================= role assignment + weight fill =================
    const bool rec = (clu < 3);
    int xi = 0, par = 0, up = 0;
    const float* W; const float* fbi = bih2; const float* fbh = bhh2;
    if (rec) {
        W = (clu == 0) ? Whh1 : (clu == 1) ? Whh2 : Whh3;
    } else {
        int f = clu - 3; xi = f >> 1; par = f & 1; up = xi;
        W = (xi == 0) ? Wih2 : Wih3;
        fbi = (xi == 0) ? bih2 : bih3; fbh = (xi == 0) ? bhh2 : bhh3;
    }

    // 4 rows in regs (64 ULL = 128 regs), 4 rows in smem (128 KB)
    ULL wreg[64];
    float fb[8];
    #pragma unroll
    for (int i = 0; i < 4; i++) {
        int rl = w * 16 + hf * 8 + i;
        size_t R = (size_t)((rl >> 5) * Hn + crank * 32 + (rl & 31));
        #pragma unroll
        for (int j = 0; j < 16; j++)
            wreg[i * 16 + j] = *(const ULL*)(W + R * Hn + l16 * 32 + j * 2);
    }
    #pragma unroll
    for (int s = 0; s < 4; s++) {
        int rl = w * 16 + hf * 8 + 4 + s;
        size_t R = (size_t)((rl >> 5) * Hn + crank * 32 + (rl & 31));
        #pragma unroll
        for (int j = 0; j < 16; j++)
            wsm[(((w * 4 + s) * 16 + j) << 5) + lane] = *(const ULL*)(W + R * Hn + l16 * 32 + j * 2);
    }
    #pragma unroll
    for (int i = 0; i < 8; i++) {
        int rl = w * 16 + hf * 8 + i;
        int R = (rl >> 5) * Hn + crank * 32 + (rl & 31);
        fb[i] = rec ? 0.0f : (fbi[R] + fbh[R]);
    }

    *(float4*)&hbuf[tid * 4] = make_float4(0.f, 0.f, 0.f, 0.f);
    if (rec && tid == 0) { mbar_init(smem_u32(&mbar[0]), 16); mbar_init(smem_u32(&mbar[1]), 16); }
    __syncthreads();
    if (rec) {
        asm volatile("barrier.cluster.arrive.aligned;" ::: "memory");
        asm volatile("barrier.cluster.wait.aligned;" ::: "memory");
    }

    // one-time global barrier
    if (tid == 0) {
        __threadfence();
        ULL old = atomicAdd(&g_cnt[0], 1ULL);
        if (old == (ULL)(NCTA - 1)) {
            g_cnt[0] = 0ULL; __threadfence(); atomicAdd(&g_gen[0], 1ULL);
        }
        volatile ULL* p = &g_gen[0];
        while (*p < sg + 1) { }
        __threadfence();
    }
    __syncthreads();

    if (rec) {
        // ================= recurrent cluster, layer = clu =================
        const unsigned hb = sbh[clu];
        unsigned* myf = &g_hflag[clu][crank][0];
        float* hout = g_h[clu];
        const float* Xs = g_X[clu];
        const unsigned* xf0 = (clu > 0) ? &g_xflag[clu-1][0][crank][0] : (const unsigned*)0;
        const unsigned* xf1 = (clu > 0) ? &g_xflag[clu-1][1][crank][0] : (const unsigned*)0;
        const unsigned xb0 = (clu > 0) ? sbx[(clu-1)*2+0] : 0u;
        const unsigned xb1 = (clu > 0) ? sbx[(clu-1)*2+1] : 0u;

        const uint32_t mb0 = smem_u32(&mbar[0]);
        // swizzled target: lane's float (g = crank*32+lane) lives at (lane>>1)*32 + crank*2 + (lane&1)
        const uint32_t hsl = smem_u32(&hbuf[(lane >> 1) * 32 + crank * 2 + (lane & 1)]);
        const uint32_t rdA = mapa_rank(hsl, (uint32_t)w);
        const uint32_t rdB = mapa_rank(hsl, (uint32_t)(w + 8));
        const uint32_t baA = mapa_rank(mb0, (uint32_t)w);
        const uint32_t baB = mapa_rank(mb0, (uint32_t)(w + 8));
        float creg = 0.0f;

        for (int t = 0; t < Tn; t++) {
            if (tid >= 224) {      // warp 7: X loaders (poll feeder flag for layers 1/2)
                int idx = tid - 224, gate = idx >> 3, ch = idx & 7;
                if (clu > 0) {
                    const unsigned* fp = (t & 1) ? xf1 : xf0;
                    unsigned tgt = ((t & 1) ? xb1 : xb0) + (unsigned)((t >> 1) + 1);
                    while ((int)(ld_acq(fp) - tgt) < 0) { }
                }
                *(float4*)&xbuf[gate * 32 + ch * 4] =
                    *(const float4*)(Xs + (size_t)t * 2048 + gate * 512 + crank * 32 + ch * 4);
            }
            if (t > 0 && tid == 0)
                mbar_wait(mb0 + ((t - 1) & 1) * 8, (unsigned)(((t - 1) >> 1) & 1));
            __syncthreads();

            // conflict-free swizzled read: hsrc[j*16 + l16]
            const ULL* hsrc = (const ULL*)(hbuf + ((t + 1) & 1) * 512);
            ULL a0=0,a1=0,a2=0,a3=0,a4=0,a5=0,a6=0,a7=0;
            #pragma unroll
            for (int j = 0; j < 16; j++) {
                ULL hv = hsrc[j * 16 + l16];
                ffma2(a0, wreg[j], hv);       ffma2(a1, wreg[16+j], hv);
                ffma2(a2, wreg[32+j], hv);    ffma2(a3, wreg[48+j], hv);
                ffma2(a4, wsm[(((w*4+0)*16+j)<<5)+lane], hv);
                ffma2(a5, wsm[(((w*4+1)*16+j)<<5)+lane], hv);
                ffma2(a6, wsm[(((w*4+2)*16+j)<<5)+lane], hv);
                ffma2(a7, wsm[(((w*4+3)*16+j)<<5)+lane], hv);
            }
            float r0=f2lo(a0)+f2hi(a0), r1=f2lo(a1)+f2hi(a1), r2=f2lo(a2)+f2hi(a2), r3=f2lo(a3)+f2hi(a3);
            float r4=f2lo(a4)+f2hi(a4), r5=f2lo(a5)+f2hi(a5), r6=f2lo(a6)+f2hi(a6), r7=f2lo(a7)+f2hi(a7);
            RED16(r0) RED16(r1) RED16(r2) RED16(r3) RED16(r4) RED16(r5) RED16(r6) RED16(r7)
            if (l16 == 0) {
                int rb = w * 16 + hf * 8;
                sp[rb]=r0; sp[rb+1]=r1; sp[rb+2]=r2; sp[rb+3]=r3;
                sp[rb+4]=r4; sp[rb+5]=r5; sp[rb+6]=r6; sp[rb+7]=r7;
            }
            __syncthreads();

            if (tid < 32) {
                float pi = sp[tid] + xbuf[tid];
                float pf = sp[32+tid] + xbuf[32+tid];
                float pg = sp[64+tid] + xbuf[64+tid];
                float po = sp[96+tid] + xbuf[96+tid];
                float iv = fast_sig(pi), fv = fast_sig(pf);
                float gg = fast_tanh(pg), ov = fast_sig(po);
                creg = fmaf(fv, creg, iv * gg);
                float h = ov * fast_tanh(creg);
                hstage[tid] = h;
                hout[(size_t)t * Hn + crank * 32 + tid] = h;
            }
            __syncthreads();

            {   // distribute h chunk (swizzled targets): warp w -> ranks w and w+8
                float hv = hstage[lane];
                unsigned off = (unsigned)(t & 1) * 2048u;
                st_cluster_f32(rdA + off, hv);
                st_cluster_f32(rdB + off, hv);
                __syncwarp();
                asm volatile("fence.acq_rel.cluster;" ::: "memory");
                if (lane == 0) {
                    unsigned bo = (unsigned)(t & 1) * 8u;
                    mbar_arrive_cl(baA + bo);
                    mbar_arrive_cl(baB + bo);
                }
            }
            if (tid == 0) st_rel(myf, hb + (unsigned)(t + 1));
        }
        asm volatile("barrier.cluster.arrive.aligned;" ::: "memory");
        asm volatile("barrier.cluster.wait.aligned;" ::: "memory");
    } else {
        // ================= feeder: X[xi+1][t] = W . g_h[up][t] + b, parity par =================
        const unsigned ub = sbh[up];
        const unsigned xb = sbx[xi * 2 + par];
        unsigned* myf = &g_xflag[xi][par][crank][0];
        float* Xd = g_X[xi + 1];
        const float* hg = g_h[up];
        ULL* hb_ull = (ULL*)hbuf;

        for (int t = par; t < Tn; t += 2) {
            if (tid < 16) {
                unsigned tgt = ub + (unsigned)(t + 1);
                const unsigned* fp = &g_hflag[up][tid][0];
                while ((int)(ld_acq(fp) - tgt) < 0) { }
            }
            __syncthreads();
            if (tid < 128) {    // coalesced load, swizzled store
                float4 v = *(const float4*)(hg + (size_t)t * Hn + tid * 4);
                int k0 = 2 * tid, k1 = 2 * tid + 1;
                ULL u0, u1;
                u0 = ((ULL)__float_as_uint(v.y) << 32) | __float_as_uint(v.x);
                u1 = ((ULL)__float_as_uint(v.w) << 32) | __float_as_uint(v.z);
                hb_ull[((k0 & 15) << 4) | (k0 >> 4)] = u0;
                hb_ull[((k1 & 15) << 4) | (k1 >> 4)] = u1;
            }
            __syncthreads();

            const ULL* hsrc = hb_ull;
            ULL a0=0,a1=0,a2=0,a3=0,a4=0,a5=0,a6=0,a7=0;
            #pragma unroll
            for (int j = 0; j < 16; j++) {
                ULL hv = hsrc[j * 16 + l16];
                ffma2(a0, wreg[j], hv);       ffma2(a1, wreg[16+j], hv);
                ffma2(a2, wreg[32+j], hv);    ffma2(a3, wreg[48+j], hv);
                ffma2(a4, wsm[(((w*4+0)*16+j)<<5)+lane], hv);
                ffma2(a5, wsm[(((w*4+1)*16+j)<<5)+lane], hv);
                ffma2(a6, wsm[(((w*4+2)*16+j)<<5)+lane], hv);
                ffma2(a7, wsm[(((w*4+3)*16+j)<<5)+lane], hv);
            }
            float rr[8];
            rr[0]=f2lo(a0)+f2hi(a0); rr[1]=f2lo(a1)+f2hi(a1); rr[2]=f2lo(a2)+f2hi(a2); rr[3]=f2lo(a3)+f2hi(a3);
            rr[4]=f2lo(a4)+f2hi(a4); rr[5]=f2lo(a5)+f2hi(a5); rr[6]=f2lo(a6)+f2hi(a6); rr[7]=f2lo(a7)+f2hi(a7);
            #pragma unroll
            for (int i = 0; i < 8; i++) { RED16(rr[i]) }
            if (l16 == 0) {
                int rb = w * 16 + hf * 8;
                #pragma unroll
                for (int i = 0; i < 8; i++) {
                    int rl = rb + i;
                    Xd[(size_t)t * 2048 + (rl >> 5) * 512 + crank * 32 + (rl & 31)] = rr[i] + fb[i];
                }
            }
            __syncthreads();
            if (tid == 0) st_rel(myf, xb + (unsigned)((t >> 1) + 1));
        }
    }

    // ================= final projection (all CTAs) =================
    if (tid < 16) {
        unsigned tgt = sbh[2] + (unsigned)Tn;
        const unsigned* fp = &g_hflag[2][tid][0];
        while ((int)(ld_acq(fp) - tgt) < 0) { }
    }
    __syncthreads();

    ULL wo[32];
    float bo4[4];
    #pragma unroll
    for (int oi = 0; oi < 4; oi++) {
        int o = w * 4 + oi;
        #pragma unroll
        for (int j = 0; j < 8; j++)
            wo[oi * 8 + j] = *(const ULL*)(Wout + (size_t)o * Hn + j * 64 + lane * 2);
        bo4[oi] = bout[o];
    }
    const float* h3 = g_h[2];
    for (int t = cta; t < Tn; t += NCTA) {
        __syncthreads();
        if (tid < 128)
            *(float4*)&hbuf[tid * 4] = *(const float4*)(h3 + (size_t)t * Hn + tid * 4);
        __syncthreads();
        const ULL* hh = (const ULL*)hbuf;
        #pragma unroll
        for (int oi = 0; oi < 4; oi++) {
            ULL acc = 0;
            #pragma unroll
            for (int j = 0; j < 8; j++) ffma2(acc, wo[oi * 8 + j], hh[j * 32 + lane]);
            float r = f2lo(acc) + f2hi(acc);
            RED32(r)
            if (lane == 0) out[(size_t)t * OUTn + w * 4 + oi] = r + bo4[oi];
        }
    }
}

extern "C" void kernel_launch(void* const* d_in, const int* in_sizes, int n_in,
                              void* d_out, int out_size) {
    const float* seq  = (const float*)d_in[0];
    const float* Wih1 = (const float*)d_in[1];
    const float* Whh1 = (const float*)d_in[2];
    const float* bih1 = (const float*)d_in[3];
    const float* bhh1 = (const float*)d_in[4];
    const float* Wih2 = (const float*)d_in[5];
    const float* Whh2 = (const float*)d_in[6];
    const float* bih2 = (const float*)d_in[7];
    const float* bhh2 = (const float*)d_in[8];
    const float* Wih3 = (const float*)d_in[9];
    const float* Whh3 = (const float*)d_in[10];
    const float* bih3 = (const float*)d_in[11];
    const float* bhh3 = (const float*)d_in[12];
    const float* Wout = (const float*)d_in[13];
    const float* bout = (const float*)d_in[14];
    float* out = (float*)d_out;

    cudaFuncSetAttribute(lstm_cluster2_kernel, cudaFuncAttributeMaxDynamicSharedMemorySize, SMEM_SZ);
    cudaFuncSetAttribute(lstm_cluster2_kernel, cudaFuncAttributeNonPortableClusterSizeAllowed, 1);

    cudaLaunchConfig_t cfg = {};
    cfg.gridDim = {NCTA, 1, 1};
    cfg.blockDim = {TPB, 1, 1};
    cfg.dynamicSmemBytes = SMEM_SZ;
    cudaLaunchAttribute at[1];
    at[0].id = cudaLaunchAttributeClusterDimension;
    at[0].val.clusterDim = {CLC, 1, 1};
    cfg.attrs = at;
    cfg.numAttrs = 1;

    cudaLaunchKernelEx(&cfg, lstm_cluster2_kernel, seq,
        Wih1, Whh1, bih1, bhh1,
        Wih2, Whh2, bih2, bhh2,
        Wih3, Whh3, bih3, bhh3,
        Wout, bout, out);
}